// round 13
// baseline (speedup 1.0000x reference)
#include <cuda_runtime.h>
#include <cuda_fp16.h>
#include <cstdint>

// Problem constants: B=8, C=64, H=W=256
#define NB 8
#define NC 64
#define NP 65536              // H*W
#define HW 256                // H (== W)
#define CW 16384              // C*W
#define C2ELEMS (NB*NC*NP)    // 33554432
#define SELEMS  (NB*HW*HW)    // 524288
#define EPSBN 1e-5f
#define SLOPE 0.2f

// ---------------- scratch (device globals; no allocation allowed) -------------
__device__ float g_w1f[NC];
__device__ float g_b1f;
__device__ __half g_wAh[NC*NC];   // [o][c], fp16, BN-folded
__device__ float g_bAf[NC];
__device__ __half g_wOh[NC*NC];   // [o][c], fp16, BN-folded
__device__ float g_bOf[NC];
__device__ float g_C1[NB*NP];                 // (B,H,W)  2MB
__device__ __half g_C2h[C2ELEMS];             // fp16 C2 (GEMM B + residual), 67MB
__device__ float g_G[2*NB*HW*HW];             // gram matrices, 4MB
__device__ __half g_S12h[SELEMS];             // S1+S2 in fp16 (k34 GEMM A), 1MB

__device__ __forceinline__ float lrelu(float y) { return y >= 0.f ? y : SLOPE * y; }

__device__ __forceinline__ void mma_f16(float acc[4],
                                        uint32_t a0, uint32_t a1, uint32_t a2, uint32_t a3,
                                        uint32_t b0, uint32_t b1) {
    asm volatile(
        "mma.sync.aligned.m16n8k16.row.col.f32.f16.f16.f32 "
        "{%0,%1,%2,%3}, {%4,%5,%6,%7}, {%8,%9}, {%0,%1,%2,%3};"
        : "+f"(acc[0]), "+f"(acc[1]), "+f"(acc[2]), "+f"(acc[3])
        : "r"(a0), "r"(a1), "r"(a2), "r"(a3), "r"(b0), "r"(b1));
}

__device__ __forceinline__ void cp_async16(void* smem_dst, const void* gsrc) {
    uint32_t s = (uint32_t)__cvta_generic_to_shared(smem_dst);
    asm volatile("cp.async.cg.shared.global [%0], [%1], 16;" :: "r"(s), "l"(gsrc));
}

__device__ __forceinline__ void ldmx4(uint32_t r[4], const __half* p) {
    uint32_t ad = (uint32_t)__cvta_generic_to_shared(p);
    asm volatile("ldmatrix.sync.aligned.m8n8.x4.shared.b16 {%0,%1,%2,%3}, [%4];"
        : "=r"(r[0]), "=r"(r[1]), "=r"(r[2]), "=r"(r[3]) : "r"(ad));
}
__device__ __forceinline__ void ldmx4t(uint32_t r[4], const __half* p) {
    uint32_t ad = (uint32_t)__cvta_generic_to_shared(p);
    asm volatile("ldmatrix.sync.aligned.m8n8.x4.trans.shared.b16 {%0,%1,%2,%3}, [%4];"
        : "=r"(r[0]), "=r"(r[1]), "=r"(r[2]), "=r"(r[3]) : "r"(ad));
}

// ---------------- K0: fold BN into conv weights; fp16-round -------------------
__global__ void k0_fold(const float* __restrict__ w1, const float* __restrict__ b1,
                        const float* __restrict__ g1, const float* __restrict__ be1,
                        const float* __restrict__ m1, const float* __restrict__ v1,
                        const float* __restrict__ wA, const float* __restrict__ bA,
                        const float* __restrict__ gA, const float* __restrict__ beA,
                        const float* __restrict__ mA, const float* __restrict__ vA,
                        const float* __restrict__ wO, const float* __restrict__ bO,
                        const float* __restrict__ gO, const float* __restrict__ beO,
                        const float* __restrict__ mO, const float* __restrict__ vO) {
    int o = threadIdx.x;  // 0..63
    float aA = gA[o] * rsqrtf(vA[o] + EPSBN);
    float aO = gO[o] * rsqrtf(vO[o] + EPSBN);
    for (int c = 0; c < NC; c++) {
        g_wAh[o*NC + c] = __float2half_rn(aA * wA[o*NC + c]);
        g_wOh[o*NC + c] = __float2half_rn(aO * wO[o*NC + c]);
    }
    g_bAf[o] = aA * (bA[o] - mA[o]) + beA[o];
    g_bOf[o] = aO * (bO[o] - mO[o]) + beO[o];
    float a1 = g1[0] * rsqrtf(v1[0] + EPSBN);
    g_w1f[o] = a1 * w1[o];
    if (o == 0) g_b1f = a1 * (b1[0] - m1[0]) + be1[0];
}

// ---------------- K1: fused C1 (fp32) + C2 conv via fp16 k16 MMA --------------
__global__ __launch_bounds__(256) void k1_c1c2(const float* __restrict__ x) {
    extern __shared__ char k1sm[];
    float* xs = (float*)k1sm;                    // [64][132]
    __half* xh = (__half*)(k1sm + 33792);        // [64][136]
    int b = blockIdx.y;
    int p0 = blockIdx.x * 128;
    int tid = threadIdx.x;

    const float* xb = x + (size_t)b * NC * NP;
    #pragma unroll
    for (int t = 0; t < 8; t++) {
        int i = tid + t*256;
        int c = i >> 5, pq = i & 31;
        float4 v = *(const float4*)(xb + (size_t)c*NP + p0 + pq*4);
        *(float4*)&xs[c*132 + pq*4] = v;
        uint2 h;
        __half2 h0 = __floats2half2_rn(v.x, v.y);
        __half2 h1 = __floats2half2_rn(v.z, v.w);
        h.x = *(uint32_t*)&h0; h.y = *(uint32_t*)&h1;
        *(uint2*)&xh[c*136 + pq*4] = h;
    }
    __syncthreads();

    if (tid < 128) {
        float s = 0.f;
        #pragma unroll
        for (int c = 0; c < NC; c++) s += g_w1f[c] * xs[c*132 + tid];
        s += g_b1f;
        g_C1[(size_t)b*NP + p0 + tid] = lrelu(s);
    }

    int lane = tid & 31, warp = tid >> 5;
    int wm = warp >> 1;
    int wn = warp & 1;
    int g = lane >> 2, tig = lane & 3;
    int r0 = wm*16 + g;
    int b_row = ((lane >> 3) & 1) * 8 + (lane & 7);
    int b_col8 = (lane >> 4) * 8;

    float acc[8][4];
    #pragma unroll
    for (int nf = 0; nf < 8; nf++)
        #pragma unroll
        for (int r = 0; r < 4; r++) acc[nf][r] = 0.f;

    #pragma unroll
    for (int kf = 0; kf < 4; kf++) {
        int kk = kf*16;
        uint32_t a0 = *(const uint32_t*)&g_wAh[r0*NC + kk + 2*tig];
        uint32_t a1 = *(const uint32_t*)&g_wAh[(r0+8)*NC + kk + 2*tig];
        uint32_t a2 = *(const uint32_t*)&g_wAh[r0*NC + kk + 2*tig + 8];
        uint32_t a3 = *(const uint32_t*)&g_wAh[(r0+8)*NC + kk + 2*tig + 8];
        #pragma unroll
        for (int nb = 0; nb < 4; nb++) {
            uint32_t bb[4];
            ldmx4t(bb, &xh[(kk + b_row)*136 + wn*64 + nb*16 + b_col8]);
            mma_f16(acc[nb*2],   a0, a1, a2, a3, bb[0], bb[1]);
            mma_f16(acc[nb*2+1], a0, a1, a2, a3, bb[2], bb[3]);
        }
    }

    int o0 = wm*16 + g, o1 = o0 + 8;
    float bo0 = g_bAf[o0], bo1 = g_bAf[o1];
    #pragma unroll
    for (int nf = 0; nf < 8; nf++) {
        int col = p0 + wn*64 + nf*8 + tig*2;
        size_t off0 = (size_t)b*NC*NP + (size_t)o0*NP + col;
        size_t off1 = (size_t)b*NC*NP + (size_t)o1*NP + col;
        *(__half2*)&g_C2h[off0] = __floats2half2_rn(lrelu(acc[nf][0] + bo0),
                                                    lrelu(acc[nf][1] + bo0));
        *(__half2*)&g_C2h[off1] = __floats2half2_rn(lrelu(acc[nf][2] + bo1),
                                                    lrelu(acc[nf][3] + bo1));
    }
}
#define K1_SMEM 51200

// ---------------- K2a: Gram matrices G1 = C1 C1^T, G2 = C1^T C1 ---------------
__global__ __launch_bounds__(256) void k2a_gram() {
    int mat = blockIdx.z & 1;
    int b = blockIdx.z >> 1;
    int j0 = blockIdx.x * 64;
    int i0 = blockIdx.y * 64;
    __shared__ float As[32][64];
    __shared__ float Bs[32][64];
    const float* A = g_C1 + (size_t)b * NP;
    int tid = threadIdx.x;
    int ti = tid >> 4, tj = tid & 15;
    float acc[4][4];
    #pragma unroll
    for (int r = 0; r < 4; r++)
        #pragma unroll
        for (int c = 0; c < 4; c++) acc[r][c] = 0.f;

    for (int k0 = 0; k0 < HW; k0 += 32) {
        if (mat == 0) {
            int i = tid >> 2;
            int kq = (tid & 3) * 8;
            float4 va0 = *(const float4*)&A[(i0+i)*HW + k0 + kq];
            float4 va1 = *(const float4*)&A[(i0+i)*HW + k0 + kq + 4];
            As[kq+0][i]=va0.x; As[kq+1][i]=va0.y; As[kq+2][i]=va0.z; As[kq+3][i]=va0.w;
            As[kq+4][i]=va1.x; As[kq+5][i]=va1.y; As[kq+6][i]=va1.z; As[kq+7][i]=va1.w;
            float4 vb0 = *(const float4*)&A[(j0+i)*HW + k0 + kq];
            float4 vb1 = *(const float4*)&A[(j0+i)*HW + k0 + kq + 4];
            Bs[kq+0][i]=vb0.x; Bs[kq+1][i]=vb0.y; Bs[kq+2][i]=vb0.z; Bs[kq+3][i]=vb0.w;
            Bs[kq+4][i]=vb1.x; Bs[kq+5][i]=vb1.y; Bs[kq+6][i]=vb1.z; Bs[kq+7][i]=vb1.w;
        } else {
            int k = tid >> 3, iq = (tid & 7) * 8;
            *(float4*)&As[k][iq]   = *(const float4*)&A[(k0+k)*HW + i0 + iq];
            *(float4*)&As[k][iq+4] = *(const float4*)&A[(k0+k)*HW + i0 + iq + 4];
            *(float4*)&Bs[k][iq]   = *(const float4*)&A[(k0+k)*HW + j0 + iq];
            *(float4*)&Bs[k][iq+4] = *(const float4*)&A[(k0+k)*HW + j0 + iq + 4];
        }
        __syncthreads();
        #pragma unroll
        for (int kk = 0; kk < 32; kk++) {
            float4 a4 = *(float4*)&As[kk][ti*4];
            float4 b4 = *(float4*)&Bs[kk][tj*4];
            float av[4] = {a4.x,a4.y,a4.z,a4.w};
            float bv[4] = {b4.x,b4.y,b4.z,b4.w};
            #pragma unroll
            for (int r = 0; r < 4; r++)
                #pragma unroll
                for (int c = 0; c < 4; c++) acc[r][c] = fmaf(av[r], bv[c], acc[r][c]);
        }
        __syncthreads();
    }
    float* G = g_G + ((size_t)(mat*NB + b)) * HW * HW;
    #pragma unroll
    for (int r = 0; r < 4; r++) {
        float4 v; v.x=acc[r][0]; v.y=acc[r][1]; v.z=acc[r][2]; v.w=acc[r][3];
        *(float4*)&G[(i0 + ti*4 + r)*HW + j0 + tj*4] = v;
    }
}

// ---------------- K2b: row softmax -> S1,S2 (outputs), S12 (fp16) -------------
__global__ __launch_bounds__(256) void k2b_softmax(float* __restrict__ S1o,
                                                   float* __restrict__ S2o) {
    int i = blockIdx.x, b = blockIdx.y, tid = threadIdx.x;
    __shared__ float red[8];
    __shared__ float bc;
    float rr[2];
    #pragma unroll
    for (int mat = 0; mat < 2; mat++) {
        float v = g_G[(((size_t)(mat*NB + b))*HW + i)*HW + tid];
        float m = v;
        #pragma unroll
        for (int o = 16; o; o >>= 1) m = fmaxf(m, __shfl_xor_sync(0xffffffffu, m, o));
        if ((tid & 31) == 0) red[tid >> 5] = m;
        __syncthreads();
        if (tid == 0) {
            float t = red[0];
            #pragma unroll
            for (int j = 1; j < 8; j++) t = fmaxf(t, red[j]);
            bc = t;
        }
        __syncthreads();
        float e = expf(v - bc);
        float s = e;
        #pragma unroll
        for (int o = 16; o; o >>= 1) s += __shfl_xor_sync(0xffffffffu, s, o);
        if ((tid & 31) == 0) red[tid >> 5] = s;
        __syncthreads();
        if (tid == 0) {
            float t = 0.f;
            #pragma unroll
            for (int j = 0; j < 8; j++) t += red[j];
            bc = t;
        }
        __syncthreads();
        rr[mat] = e / bc;
        float* dst = mat == 0 ? S1o : S2o;
        dst[((size_t)b*HW + i)*HW + tid] = rr[mat];
        __syncthreads();
    }
    g_S12h[((size_t)b*HW + i)*HW + tid] = __float2half_rn(rr[0] + rr[1]);
}

// ---------------- K34: fused M = S12 @ C2view (fp16 HMMA), fp16 conv, residual -
// Block: all 256 GEMM rows x 64 cols. grid (256, 1, NB), 256 thr (8 warps).
// 3-stage cp.async ring: stage = As[256][40] + Bs[32][72] halves = 25088 B each;
// 3 stages = 75264 B. Conv staging ms[64][264] fp16 (33792 B) aliases ring after
// the final post-loop sync. One __syncthreads per k-iteration.
__global__ __launch_bounds__(256) void k34_fused(float* __restrict__ out) {
    extern __shared__ char sm_raw[];
    __half* ring = (__half*)sm_raw;
    __half* ms = (__half*)sm_raw;                // [64][264]
    const int STG = 12544;                       // halves per stage
    int b = blockIdx.z;
    int n0 = blockIdx.x * 64;
    const __half* Ag = g_S12h + (size_t)b * HW * HW;
    const __half* Bg = g_C2h + (size_t)b * NC * NP;
    int tid = threadIdx.x;
    int lane = tid & 31;
    int warp = tid >> 5;                         // GEMM m rows warp*32..+31
    int g = lane >> 2, tig = lane & 3;

    // loader indices: A 256x32 halves = 1024 16B-chunks (4/thread); B 32x64 = 256 (1/thread)
    int arow[4], aq[4];
    #pragma unroll
    for (int t = 0; t < 4; t++) { int idx = tid + t*256; arow[t] = idx >> 2; aq[t] = (idx & 3) * 8; }
    int brow = tid >> 3, bq = (tid & 7) * 8;

    // ldmatrix lane address components
    int a_row = warp*32 + (lane & 15);           // + mf*16
    int a_col8 = (lane >> 4) * 8;                // + kf*16
    int b_row = ((lane >> 3) & 1) * 8 + (lane & 7);  // + kf*16
    int b_col8 = (lane >> 4) * 8;                // + nb*16

    // prologue: stages 0,1 <- k chunks 0,1
    #pragma unroll
    for (int s = 0; s < 2; s++) {
        __half* Ad = ring + s*STG;
        __half* Bd = Ad + 10240;
        int kn = s*32;
        #pragma unroll
        for (int t = 0; t < 4; t++)
            cp_async16(&Ad[arow[t]*40 + aq[t]], &Ag[(size_t)arow[t]*HW + kn + aq[t]]);
        cp_async16(&Bd[brow*72 + bq], &Bg[(size_t)(kn+brow)*CW + n0 + bq]);
        asm volatile("cp.async.commit_group;");
    }

    float acc[2][8][4];
    #pragma unroll
    for (int mf = 0; mf < 2; mf++)
        #pragma unroll
        for (int nf = 0; nf < 8; nf++)
            #pragma unroll
            for (int r = 0; r < 4; r++) acc[mf][nf][r] = 0.f;

    for (int i = 0; i < 8; i++) {
        // stage i ready when pending <= 1 (stage i+1 may still be in flight);
        // at the last iteration nothing else is in flight -> wait 0.
        if (i < 7) asm volatile("cp.async.wait_group 1;");
        else       asm volatile("cp.async.wait_group 0;");
        __syncthreads();   // all threads done consuming stage (i-1)%3; stage i visible

        if (i + 2 <= 7) {  // prefetch stage (i+2)%3 (== (i-1)%3, now safe to overwrite)
            __half* Ad = ring + ((i+2)%3)*STG;
            __half* Bd = Ad + 10240;
            int kn = (i+2)*32;
            #pragma unroll
            for (int t = 0; t < 4; t++)
                cp_async16(&Ad[arow[t]*40 + aq[t]], &Ag[(size_t)arow[t]*HW + kn + aq[t]]);
            cp_async16(&Bd[brow*72 + bq], &Bg[(size_t)(kn+brow)*CW + n0 + bq]);
            asm volatile("cp.async.commit_group;");
        }

        const __half* As = ring + (i%3)*STG;
        const __half* Bs = As + 10240;

        #pragma unroll
        for (int kf = 0; kf < 2; kf++) {
            uint32_t a[2][4];
            #pragma unroll
            for (int mf = 0; mf < 2; mf++)
                ldmx4(a[mf], &As[(a_row + mf*16)*40 + kf*16 + a_col8]);
            #pragma unroll
            for (int nb = 0; nb < 4; nb++) {
                uint32_t bb[4];
                ldmx4t(bb, &Bs[(kf*16 + b_row)*72 + nb*16 + b_col8]);
                #pragma unroll
                for (int mf = 0; mf < 2; mf++) {
                    mma_f16(acc[mf][nb*2],   a[mf][0], a[mf][1], a[mf][2], a[mf][3], bb[0], bb[1]);
                    mma_f16(acc[mf][nb*2+1], a[mf][0], a[mf][1], a[mf][2], a[mf][3], bb[2], bb[3]);
                }
            }
        }
    }
    __syncthreads();   // all MMA reads of the ring done before ms overwrites it

    // Stage accumulators to smem (fp16) in conv layout: row m -> (c = m>>2, hh = m&3)
    #pragma unroll
    for (int mf = 0; mf < 2; mf++) {
        #pragma unroll
        for (int nf = 0; nf < 8; nf++) {
            int row0 = warp*32 + mf*16 + g;
            int row1 = row0 + 8;
            int col  = nf*8 + tig*2;
            int c0 = row0 >> 2, hh0 = row0 & 3;
            int c1 = row1 >> 2, hh1 = row1 & 3;
            *(__half2*)&ms[c0*264 + hh0*64 + col] = __floats2half2_rn(acc[mf][nf][0], acc[mf][nf][1]);
            *(__half2*)&ms[c1*264 + hh1*64 + col] = __floats2half2_rn(acc[mf][nf][2], acc[mf][nf][3]);
        }
    }
    __syncthreads();

    // Conv phase (fp16 k16): 8 warps as 4(m: o) x 2(n: pix), warp tile 16x64, 2 halves.
    int wm = warp >> 1;
    int wn = warp & 1;
    int r0 = wm*16 + g;
    int o0 = r0, o1 = r0 + 8;
    float bo0 = g_bOf[o0], bo1 = g_bOf[o1];
    size_t bofs = (size_t)b * NC * NP;

    #pragma unroll
    for (int ph = 0; ph < 2; ph++) {
        int pix_base = ph*128 + wn*64;
        float acc2[8][4];
        #pragma unroll
        for (int nf = 0; nf < 8; nf++)
            #pragma unroll
            for (int r = 0; r < 4; r++) acc2[nf][r] = 0.f;

        #pragma unroll
        for (int kf = 0; kf < 4; kf++) {
            int kk = kf*16;
            uint32_t a0 = *(const uint32_t*)&g_wOh[r0*NC + kk + 2*tig];
            uint32_t a1 = *(const uint32_t*)&g_wOh[(r0+8)*NC + kk + 2*tig];
            uint32_t a2 = *(const uint32_t*)&g_wOh[r0*NC + kk + 2*tig + 8];
            uint32_t a3 = *(const uint32_t*)&g_wOh[(r0+8)*NC + kk + 2*tig + 8];
            #pragma unroll
            for (int nb = 0; nb < 4; nb++) {
                uint32_t bb[4];
                ldmx4t(bb, &ms[(kk + b_row)*264 + pix_base + nb*16 + b_col8]);
                mma_f16(acc2[nb*2],   a0, a1, a2, a3, bb[0], bb[1]);
                mma_f16(acc2[nb*2+1], a0, a1, a2, a3, bb[2], bb[3]);
            }
        }

        #pragma unroll
        for (int nf = 0; nf < 8; nf++) {
            int pix = pix_base + nf*8 + tig*2;
            int hh = pix >> 6, wl = pix & 63;
            size_t off0 = bofs + (size_t)(o0*4 + hh)*CW + n0 + wl;
            size_t off1 = bofs + (size_t)(o1*4 + hh)*CW + n0 + wl;
            float2 c20 = __half22float2(*(const __half2*)&g_C2h[off0]);
            float2 c21 = __half22float2(*(const __half2*)&g_C2h[off1]);
            float2 v0, v1;
            v0.x = c20.x + lrelu(acc2[nf][0] + bo0);
            v0.y = c20.y + lrelu(acc2[nf][1] + bo0);
            v1.x = c21.x + lrelu(acc2[nf][2] + bo1);
            v1.y = c21.y + lrelu(acc2[nf][3] + bo1);
            *(float2*)&out[off0] = v0;
            *(float2*)&out[off1] = v1;
        }
    }
}

#define K34_SMEM 75264

// ---------------- launch --------------------------------------------------------
extern "C" void kernel_launch(void* const* d_in, const int* in_sizes, int n_in,
                              void* d_out, int out_size) {
    const float* x   = (const float*)d_in[0];
    const float* w1  = (const float*)d_in[1];
    const float* b1  = (const float*)d_in[2];
    const float* g1  = (const float*)d_in[3];
    const float* be1 = (const float*)d_in[4];
    const float* m1  = (const float*)d_in[5];
    const float* v1  = (const float*)d_in[6];
    const float* wA  = (const float*)d_in[7];
    const float* bA  = (const float*)d_in[8];
    const float* gA  = (const float*)d_in[9];
    const float* beA = (const float*)d_in[10];
    const float* mA  = (const float*)d_in[11];
    const float* vA  = (const float*)d_in[12];
    const float* wO  = (const float*)d_in[13];
    const float* bO  = (const float*)d_in[14];
    const float* gO  = (const float*)d_in[15];
    const float* beO = (const float*)d_in[16];
    const float* mO  = (const float*)d_in[17];
    const float* vO  = (const float*)d_in[18];

    float* out = (float*)d_out;
    float* S1o = out + (size_t)C2ELEMS;
    float* S2o = S1o + (size_t)SELEMS;

    cudaFuncSetAttribute(k1_c1c2, cudaFuncAttributeMaxDynamicSharedMemorySize, K1_SMEM);
    cudaFuncSetAttribute(k34_fused, cudaFuncAttributeMaxDynamicSharedMemorySize, K34_SMEM);

    k0_fold<<<1, 64>>>(w1,b1,g1,be1,m1,v1, wA,bA,gA,beA,mA,vA, wO,bO,gO,beO,mO,vO);
    k1_c1c2<<<dim3(NP/128, NB), 256, K1_SMEM>>>(x);
    k2a_gram<<<dim3(4, 4, 2*NB), 256>>>();
    k2b_softmax<<<dim3(HW, NB), 256>>>(S1o, S2o);
    k34_fused<<<dim3(CW/64, 1, NB), 256, K34_SMEM>>>(out);
}

// round 14
// speedup vs baseline: 1.0285x; 1.0285x over previous
#include <cuda_runtime.h>
#include <cuda_fp16.h>
#include <cstdint>

// Problem constants: B=8, C=64, H=W=256
#define NB 8
#define NC 64
#define NP 65536              // H*W
#define HW 256                // H (== W)
#define CW 16384              // C*W
#define C2ELEMS (NB*NC*NP)    // 33554432
#define SELEMS  (NB*HW*HW)    // 524288
#define EPSBN 1e-5f
#define SLOPE 0.2f

// ---------------- scratch (device globals; no allocation allowed) -------------
__device__ float g_w1f[NC];
__device__ float g_b1f;
__device__ __half g_wAh[NC*NC];   // [o][c], fp16, BN-folded
__device__ float g_bAf[NC];
__device__ __half g_wOh[NC*NC];   // [o][c], fp16, BN-folded
__device__ float g_bOf[NC];
__device__ float g_C1[NB*NP];                 // (B,H,W)  2MB
__device__ __half g_C2h[C2ELEMS];             // fp16 C2 (GEMM B + residual), 67MB
__device__ float g_G[2*NB*HW*HW];             // gram matrices, 4MB
__device__ __half g_S12h[SELEMS];             // S1+S2 in fp16 (k34 GEMM A), 1MB

__device__ __forceinline__ float lrelu(float y) { return y >= 0.f ? y : SLOPE * y; }

__device__ __forceinline__ void mma_f16(float acc[4],
                                        uint32_t a0, uint32_t a1, uint32_t a2, uint32_t a3,
                                        uint32_t b0, uint32_t b1) {
    asm volatile(
        "mma.sync.aligned.m16n8k16.row.col.f32.f16.f16.f32 "
        "{%0,%1,%2,%3}, {%4,%5,%6,%7}, {%8,%9}, {%0,%1,%2,%3};"
        : "+f"(acc[0]), "+f"(acc[1]), "+f"(acc[2]), "+f"(acc[3])
        : "r"(a0), "r"(a1), "r"(a2), "r"(a3), "r"(b0), "r"(b1));
}

__device__ __forceinline__ void cp_async16(void* smem_dst, const void* gsrc) {
    uint32_t s = (uint32_t)__cvta_generic_to_shared(smem_dst);
    asm volatile("cp.async.cg.shared.global [%0], [%1], 16;" :: "r"(s), "l"(gsrc));
}

__device__ __forceinline__ void ldmx4(uint32_t r[4], const __half* p) {
    uint32_t ad = (uint32_t)__cvta_generic_to_shared(p);
    asm volatile("ldmatrix.sync.aligned.m8n8.x4.shared.b16 {%0,%1,%2,%3}, [%4];"
        : "=r"(r[0]), "=r"(r[1]), "=r"(r[2]), "=r"(r[3]) : "r"(ad));
}
__device__ __forceinline__ void ldmx4t(uint32_t r[4], const __half* p) {
    uint32_t ad = (uint32_t)__cvta_generic_to_shared(p);
    asm volatile("ldmatrix.sync.aligned.m8n8.x4.trans.shared.b16 {%0,%1,%2,%3}, [%4];"
        : "=r"(r[0]), "=r"(r[1]), "=r"(r[2]), "=r"(r[3]) : "r"(ad));
}

// ---------------- K0: fold BN into conv weights; fp16-round -------------------
__global__ void k0_fold(const float* __restrict__ w1, const float* __restrict__ b1,
                        const float* __restrict__ g1, const float* __restrict__ be1,
                        const float* __restrict__ m1, const float* __restrict__ v1,
                        const float* __restrict__ wA, const float* __restrict__ bA,
                        const float* __restrict__ gA, const float* __restrict__ beA,
                        const float* __restrict__ mA, const float* __restrict__ vA,
                        const float* __restrict__ wO, const float* __restrict__ bO,
                        const float* __restrict__ gO, const float* __restrict__ beO,
                        const float* __restrict__ mO, const float* __restrict__ vO) {
    int o = threadIdx.x;  // 0..63
    float aA = gA[o] * rsqrtf(vA[o] + EPSBN);
    float aO = gO[o] * rsqrtf(vO[o] + EPSBN);
    for (int c = 0; c < NC; c++) {
        g_wAh[o*NC + c] = __float2half_rn(aA * wA[o*NC + c]);
        g_wOh[o*NC + c] = __float2half_rn(aO * wO[o*NC + c]);
    }
    g_bAf[o] = aA * (bA[o] - mA[o]) + beA[o];
    g_bOf[o] = aO * (bO[o] - mO[o]) + beO[o];
    float a1 = g1[0] * rsqrtf(v1[0] + EPSBN);
    g_w1f[o] = a1 * w1[o];
    if (o == 0) g_b1f = a1 * (b1[0] - m1[0]) + be1[0];
}

// ---------------- K1: fused C1 (fp32) + C2 conv via fp16 k16 MMA --------------
__global__ __launch_bounds__(256) void k1_c1c2(const float* __restrict__ x) {
    extern __shared__ char k1sm[];
    float* xs = (float*)k1sm;                    // [64][132]
    __half* xh = (__half*)(k1sm + 33792);        // [64][136]
    int b = blockIdx.y;
    int p0 = blockIdx.x * 128;
    int tid = threadIdx.x;

    const float* xb = x + (size_t)b * NC * NP;
    #pragma unroll
    for (int t = 0; t < 8; t++) {
        int i = tid + t*256;
        int c = i >> 5, pq = i & 31;
        float4 v = *(const float4*)(xb + (size_t)c*NP + p0 + pq*4);
        *(float4*)&xs[c*132 + pq*4] = v;
        uint2 h;
        __half2 h0 = __floats2half2_rn(v.x, v.y);
        __half2 h1 = __floats2half2_rn(v.z, v.w);
        h.x = *(uint32_t*)&h0; h.y = *(uint32_t*)&h1;
        *(uint2*)&xh[c*136 + pq*4] = h;
    }
    __syncthreads();

    if (tid < 128) {
        float s = 0.f;
        #pragma unroll
        for (int c = 0; c < NC; c++) s += g_w1f[c] * xs[c*132 + tid];
        s += g_b1f;
        g_C1[(size_t)b*NP + p0 + tid] = lrelu(s);
    }

    int lane = tid & 31, warp = tid >> 5;
    int wm = warp >> 1;
    int wn = warp & 1;
    int g = lane >> 2, tig = lane & 3;
    int r0 = wm*16 + g;
    int b_row = ((lane >> 3) & 1) * 8 + (lane & 7);
    int b_col8 = (lane >> 4) * 8;

    float acc[8][4];
    #pragma unroll
    for (int nf = 0; nf < 8; nf++)
        #pragma unroll
        for (int r = 0; r < 4; r++) acc[nf][r] = 0.f;

    #pragma unroll
    for (int kf = 0; kf < 4; kf++) {
        int kk = kf*16;
        uint32_t a0 = *(const uint32_t*)&g_wAh[r0*NC + kk + 2*tig];
        uint32_t a1 = *(const uint32_t*)&g_wAh[(r0+8)*NC + kk + 2*tig];
        uint32_t a2 = *(const uint32_t*)&g_wAh[r0*NC + kk + 2*tig + 8];
        uint32_t a3 = *(const uint32_t*)&g_wAh[(r0+8)*NC + kk + 2*tig + 8];
        #pragma unroll
        for (int nb = 0; nb < 4; nb++) {
            uint32_t bb[4];
            ldmx4t(bb, &xh[(kk + b_row)*136 + wn*64 + nb*16 + b_col8]);
            mma_f16(acc[nb*2],   a0, a1, a2, a3, bb[0], bb[1]);
            mma_f16(acc[nb*2+1], a0, a1, a2, a3, bb[2], bb[3]);
        }
    }

    int o0 = wm*16 + g, o1 = o0 + 8;
    float bo0 = g_bAf[o0], bo1 = g_bAf[o1];
    #pragma unroll
    for (int nf = 0; nf < 8; nf++) {
        int col = p0 + wn*64 + nf*8 + tig*2;
        size_t off0 = (size_t)b*NC*NP + (size_t)o0*NP + col;
        size_t off1 = (size_t)b*NC*NP + (size_t)o1*NP + col;
        *(__half2*)&g_C2h[off0] = __floats2half2_rn(lrelu(acc[nf][0] + bo0),
                                                    lrelu(acc[nf][1] + bo0));
        *(__half2*)&g_C2h[off1] = __floats2half2_rn(lrelu(acc[nf][2] + bo1),
                                                    lrelu(acc[nf][3] + bo1));
    }
}
#define K1_SMEM 51200

// ---------------- K2a: Gram via fp16 hi/lo split tensor MMA -------------------
// G1 = C1 C1^T (mat 0), G2 = C1^T C1 (mat 1). 64x64 tile, K chunks of 32.
// grid (4,4,16), 256 thr, 8 warps as 4(m) x 2(n), warp tile 16m x 32n.
// Exact split: G = hi.hi^T + hi.lo^T + lo.hi^T (lo.lo ~ 2^-22, dropped).
__global__ __launch_bounds__(256) void k2a_gram_tc() {
    __shared__ __half Ahi[64][40], Alo[64][40];   // [i][k]
    __shared__ __half Bhi[32][72], Blo[32][72];   // [k][j]
    int mat = blockIdx.z & 1;
    int b = blockIdx.z >> 1;
    int j0 = blockIdx.x * 64;
    int i0 = blockIdx.y * 64;
    const float* A = g_C1 + (size_t)b * NP;
    int tid = threadIdx.x;
    int lane = tid & 31, warp = tid >> 5;
    int wm = warp >> 1, wn = warp & 1;
    int g = lane >> 2, tig = lane & 3;
    int r0 = wm*16 + g;
    int b_row = ((lane >> 3) & 1) * 8 + (lane & 7);
    int b_col8 = (lane >> 4) * 8;

    float acc[4][4];
    #pragma unroll
    for (int nf = 0; nf < 4; nf++)
        #pragma unroll
        for (int r = 0; r < 4; r++) acc[nf][r] = 0.f;

    for (int k0 = 0; k0 < HW; k0 += 32) {
        if (k0 > 0) __syncthreads();   // previous chunk's compute done
        if (mat == 0) {
            // A tile: rows i0+r, k contiguous. 64x32 f32 = 512 float4, 2/thread.
            #pragma unroll
            for (int t = 0; t < 2; t++) {
                int idx = tid + t*256;
                int r = idx >> 3, q = (idx & 7) * 4;
                float4 v = *(const float4*)&A[(size_t)(i0+r)*HW + k0 + q];
                float h0=__half2float(__float2half_rn(v.x));
                float h1=__half2float(__float2half_rn(v.y));
                float h2=__half2float(__float2half_rn(v.z));
                float h3=__half2float(__float2half_rn(v.w));
                *(__half2*)&Ahi[r][q]   = __floats2half2_rn(v.x, v.y);
                *(__half2*)&Ahi[r][q+2] = __floats2half2_rn(v.z, v.w);
                *(__half2*)&Alo[r][q]   = __floats2half2_rn(v.x-h0, v.y-h1);
                *(__half2*)&Alo[r][q+2] = __floats2half2_rn(v.z-h2, v.w-h3);
            }
            // B tile transposed: Bhi[k][j] = C1[j0+j][k0+k]
            #pragma unroll
            for (int t = 0; t < 2; t++) {
                int idx = tid + t*256;
                int jj = idx >> 3, q = (idx & 7) * 4;
                float4 v = *(const float4*)&A[(size_t)(j0+jj)*HW + k0 + q];
                float vv[4] = {v.x, v.y, v.z, v.w};
                #pragma unroll
                for (int e = 0; e < 4; e++) {
                    __half h = __float2half_rn(vv[e]);
                    Bhi[q+e][jj] = h;
                    Blo[q+e][jj] = __float2half_rn(vv[e] - __half2float(h));
                }
            }
        } else {
            // A transposed: Ahi[i][k] = C1[k0+k][i0+i]. Read 32 k-rows x 64 i.
            #pragma unroll
            for (int t = 0; t < 2; t++) {
                int idx = tid + t*256;
                int kk = idx >> 4, q = (idx & 15) * 4;
                float4 v = *(const float4*)&A[(size_t)(k0+kk)*HW + i0 + q];
                float vv[4] = {v.x, v.y, v.z, v.w};
                #pragma unroll
                for (int e = 0; e < 4; e++) {
                    __half h = __float2half_rn(vv[e]);
                    Ahi[q+e][kk] = h;
                    Alo[q+e][kk] = __float2half_rn(vv[e] - __half2float(h));
                }
            }
            // B natural: Bhi[k][j] = C1[k0+k][j0+j]
            #pragma unroll
            for (int t = 0; t < 2; t++) {
                int idx = tid + t*256;
                int kk = idx >> 4, q = (idx & 15) * 4;
                float4 v = *(const float4*)&A[(size_t)(k0+kk)*HW + j0 + q];
                float h0=__half2float(__float2half_rn(v.x));
                float h1=__half2float(__float2half_rn(v.y));
                float h2=__half2float(__float2half_rn(v.z));
                float h3=__half2float(__float2half_rn(v.w));
                *(__half2*)&Bhi[kk][q]   = __floats2half2_rn(v.x, v.y);
                *(__half2*)&Bhi[kk][q+2] = __floats2half2_rn(v.z, v.w);
                *(__half2*)&Blo[kk][q]   = __floats2half2_rn(v.x-h0, v.y-h1);
                *(__half2*)&Blo[kk][q+2] = __floats2half2_rn(v.z-h2, v.w-h3);
            }
        }
        __syncthreads();

        #pragma unroll
        for (int kf = 0; kf < 2; kf++) {
            int kk = kf*16;
            uint32_t ah0 = *(const uint32_t*)&Ahi[r0][kk + 2*tig];
            uint32_t ah1 = *(const uint32_t*)&Ahi[r0+8][kk + 2*tig];
            uint32_t ah2 = *(const uint32_t*)&Ahi[r0][kk + 2*tig + 8];
            uint32_t ah3 = *(const uint32_t*)&Ahi[r0+8][kk + 2*tig + 8];
            uint32_t al0 = *(const uint32_t*)&Alo[r0][kk + 2*tig];
            uint32_t al1 = *(const uint32_t*)&Alo[r0+8][kk + 2*tig];
            uint32_t al2 = *(const uint32_t*)&Alo[r0][kk + 2*tig + 8];
            uint32_t al3 = *(const uint32_t*)&Alo[r0+8][kk + 2*tig + 8];
            #pragma unroll
            for (int nb = 0; nb < 2; nb++) {
                uint32_t bh[4], bl[4];
                ldmx4t(bh, &Bhi[kk + b_row][wn*32 + nb*16 + b_col8]);
                ldmx4t(bl, &Blo[kk + b_row][wn*32 + nb*16 + b_col8]);
                // hi*hi + hi*lo + lo*hi for both n8 halves
                mma_f16(acc[nb*2],   ah0, ah1, ah2, ah3, bh[0], bh[1]);
                mma_f16(acc[nb*2],   ah0, ah1, ah2, ah3, bl[0], bl[1]);
                mma_f16(acc[nb*2],   al0, al1, al2, al3, bh[0], bh[1]);
                mma_f16(acc[nb*2+1], ah0, ah1, ah2, ah3, bh[2], bh[3]);
                mma_f16(acc[nb*2+1], ah0, ah1, ah2, ah3, bl[2], bl[3]);
                mma_f16(acc[nb*2+1], al0, al1, al2, al3, bh[2], bh[3]);
            }
        }
    }

    float* G = g_G + ((size_t)(mat*NB + b)) * HW * HW;
    int rg = i0 + wm*16 + g;
    #pragma unroll
    for (int nf = 0; nf < 4; nf++) {
        int col = j0 + wn*32 + nf*8 + tig*2;
        float2 v0; v0.x = acc[nf][0]; v0.y = acc[nf][1];
        float2 v1; v1.x = acc[nf][2]; v1.y = acc[nf][3];
        *(float2*)&G[(size_t)rg*HW + col] = v0;
        *(float2*)&G[(size_t)(rg+8)*HW + col] = v1;
    }
}

// ---------------- K2b: row softmax -> S1,S2 (outputs), S12 (fp16) -------------
__global__ __launch_bounds__(256) void k2b_softmax(float* __restrict__ S1o,
                                                   float* __restrict__ S2o) {
    int i = blockIdx.x, b = blockIdx.y, tid = threadIdx.x;
    __shared__ float red[8];
    __shared__ float bc;
    float rr[2];
    #pragma unroll
    for (int mat = 0; mat < 2; mat++) {
        float v = g_G[(((size_t)(mat*NB + b))*HW + i)*HW + tid];
        float m = v;
        #pragma unroll
        for (int o = 16; o; o >>= 1) m = fmaxf(m, __shfl_xor_sync(0xffffffffu, m, o));
        if ((tid & 31) == 0) red[tid >> 5] = m;
        __syncthreads();
        if (tid == 0) {
            float t = red[0];
            #pragma unroll
            for (int j = 1; j < 8; j++) t = fmaxf(t, red[j]);
            bc = t;
        }
        __syncthreads();
        float e = expf(v - bc);
        float s = e;
        #pragma unroll
        for (int o = 16; o; o >>= 1) s += __shfl_xor_sync(0xffffffffu, s, o);
        if ((tid & 31) == 0) red[tid >> 5] = s;
        __syncthreads();
        if (tid == 0) {
            float t = 0.f;
            #pragma unroll
            for (int j = 0; j < 8; j++) t += red[j];
            bc = t;
        }
        __syncthreads();
        rr[mat] = e / bc;
        float* dst = mat == 0 ? S1o : S2o;
        dst[((size_t)b*HW + i)*HW + tid] = rr[mat];
        __syncthreads();
    }
    g_S12h[((size_t)b*HW + i)*HW + tid] = __float2half_rn(rr[0] + rr[1]);
}

// ---------------- K34: fused M = S12 @ C2view (fp16 HMMA), fp16 conv, residual -
// R11 2-stage ring (proven 237.6us). Block: 256 GEMM rows x 64 cols.
__global__ __launch_bounds__(256) void k34_fused(float* __restrict__ out) {
    extern __shared__ char sm_raw[];
    __half* ring = (__half*)sm_raw;
    __half* ms = (__half*)sm_raw;                // [64][264]
    const int STG = 12544;
    int b = blockIdx.z;
    int n0 = blockIdx.x * 64;
    const __half* Ag = g_S12h + (size_t)b * HW * HW;
    const __half* Bg = g_C2h + (size_t)b * NC * NP;
    int tid = threadIdx.x;
    int lane = tid & 31;
    int warp = tid >> 5;
    int g = lane >> 2, tig = lane & 3;

    int arow[4], aq[4];
    #pragma unroll
    for (int t = 0; t < 4; t++) { int idx = tid + t*256; arow[t] = idx >> 2; aq[t] = (idx & 3) * 8; }
    int brow = tid >> 3, bq = (tid & 7) * 8;

    int a_row = warp*32 + (lane & 15);
    int a_col8 = (lane >> 4) * 8;
    int b_row = ((lane >> 3) & 1) * 8 + (lane & 7);
    int b_col8 = (lane >> 4) * 8;

    {
        __half* Ad = ring;
        __half* Bd = ring + 10240;
        #pragma unroll
        for (int t = 0; t < 4; t++)
            cp_async16(&Ad[arow[t]*40 + aq[t]], &Ag[(size_t)arow[t]*HW + aq[t]]);
        cp_async16(&Bd[brow*72 + bq], &Bg[(size_t)brow*CW + n0 + bq]);
        asm volatile("cp.async.commit_group;");
    }

    float acc[2][8][4];
    #pragma unroll
    for (int mf = 0; mf < 2; mf++)
        #pragma unroll
        for (int nf = 0; nf < 8; nf++)
            #pragma unroll
            for (int r = 0; r < 4; r++) acc[mf][nf][r] = 0.f;

    for (int k0 = 0; k0 < HW; k0 += 32) {
        int stg = (k0 >> 5) & 1;
        if (k0 + 32 < HW) {
            __half* Ad = ring + (stg^1)*STG;
            __half* Bd = Ad + 10240;
            int kn = k0 + 32;
            #pragma unroll
            for (int t = 0; t < 4; t++)
                cp_async16(&Ad[arow[t]*40 + aq[t]], &Ag[(size_t)arow[t]*HW + kn + aq[t]]);
            cp_async16(&Bd[brow*72 + bq], &Bg[(size_t)(kn+brow)*CW + n0 + bq]);
            asm volatile("cp.async.commit_group;");
            asm volatile("cp.async.wait_group 1;");
        } else {
            asm volatile("cp.async.wait_group 0;");
        }
        __syncthreads();

        const __half* As = ring + stg*STG;
        const __half* Bs = As + 10240;

        #pragma unroll
        for (int kf = 0; kf < 2; kf++) {
            uint32_t a[2][4];
            #pragma unroll
            for (int mf = 0; mf < 2; mf++)
                ldmx4(a[mf], &As[(a_row + mf*16)*40 + kf*16 + a_col8]);
            #pragma unroll
            for (int nb = 0; nb < 4; nb++) {
                uint32_t bb[4];
                ldmx4t(bb, &Bs[(kf*16 + b_row)*72 + nb*16 + b_col8]);
                #pragma unroll
                for (int mf = 0; mf < 2; mf++) {
                    mma_f16(acc[mf][nb*2],   a[mf][0], a[mf][1], a[mf][2], a[mf][3], bb[0], bb[1]);
                    mma_f16(acc[mf][nb*2+1], a[mf][0], a[mf][1], a[mf][2], a[mf][3], bb[2], bb[3]);
                }
            }
        }
        __syncthreads();
    }

    #pragma unroll
    for (int mf = 0; mf < 2; mf++) {
        #pragma unroll
        for (int nf = 0; nf < 8; nf++) {
            int row0 = warp*32 + mf*16 + g;
            int row1 = row0 + 8;
            int col  = nf*8 + tig*2;
            int c0 = row0 >> 2, hh0 = row0 & 3;
            int c1 = row1 >> 2, hh1 = row1 & 3;
            *(__half2*)&ms[c0*264 + hh0*64 + col] = __floats2half2_rn(acc[mf][nf][0], acc[mf][nf][1]);
            *(__half2*)&ms[c1*264 + hh1*64 + col] = __floats2half2_rn(acc[mf][nf][2], acc[mf][nf][3]);
        }
    }
    __syncthreads();

    int wm = warp >> 1;
    int wn = warp & 1;
    int r0 = wm*16 + g;
    int o0 = r0, o1 = r0 + 8;
    float bo0 = g_bOf[o0], bo1 = g_bOf[o1];
    size_t bofs = (size_t)b * NC * NP;

    #pragma unroll
    for (int ph = 0; ph < 2; ph++) {
        int pix_base = ph*128 + wn*64;
        float acc2[8][4];
        #pragma unroll
        for (int nf = 0; nf < 8; nf++)
            #pragma unroll
            for (int r = 0; r < 4; r++) acc2[nf][r] = 0.f;

        #pragma unroll
        for (int kf = 0; kf < 4; kf++) {
            int kk = kf*16;
            uint32_t a0 = *(const uint32_t*)&g_wOh[r0*NC + kk + 2*tig];
            uint32_t a1 = *(const uint32_t*)&g_wOh[(r0+8)*NC + kk + 2*tig];
            uint32_t a2 = *(const uint32_t*)&g_wOh[r0*NC + kk + 2*tig + 8];
            uint32_t a3 = *(const uint32_t*)&g_wOh[(r0+8)*NC + kk + 2*tig + 8];
            #pragma unroll
            for (int nb = 0; nb < 4; nb++) {
                uint32_t bb[4];
                ldmx4t(bb, &ms[(kk + b_row)*264 + pix_base + nb*16 + b_col8]);
                mma_f16(acc2[nb*2],   a0, a1, a2, a3, bb[0], bb[1]);
                mma_f16(acc2[nb*2+1], a0, a1, a2, a3, bb[2], bb[3]);
            }
        }

        #pragma unroll
        for (int nf = 0; nf < 8; nf++) {
            int pix = pix_base + nf*8 + tig*2;
            int hh = pix >> 6, wl = pix & 63;
            size_t off0 = bofs + (size_t)(o0*4 + hh)*CW + n0 + wl;
            size_t off1 = bofs + (size_t)(o1*4 + hh)*CW + n0 + wl;
            float2 c20 = __half22float2(*(const __half2*)&g_C2h[off0]);
            float2 c21 = __half22float2(*(const __half2*)&g_C2h[off1]);
            float2 v0, v1;
            v0.x = c20.x + lrelu(acc2[nf][0] + bo0);
            v0.y = c20.y + lrelu(acc2[nf][1] + bo0);
            v1.x = c21.x + lrelu(acc2[nf][2] + bo1);
            v1.y = c21.y + lrelu(acc2[nf][3] + bo1);
            *(float2*)&out[off0] = v0;
            *(float2*)&out[off1] = v1;
        }
    }
}

#define K34_SMEM 50176

// ---------------- launch --------------------------------------------------------
extern "C" void kernel_launch(void* const* d_in, const int* in_sizes, int n_in,
                              void* d_out, int out_size) {
    const float* x   = (const float*)d_in[0];
    const float* w1  = (const float*)d_in[1];
    const float* b1  = (const float*)d_in[2];
    const float* g1  = (const float*)d_in[3];
    const float* be1 = (const float*)d_in[4];
    const float* m1  = (const float*)d_in[5];
    const float* v1  = (const float*)d_in[6];
    const float* wA  = (const float*)d_in[7];
    const float* bA  = (const float*)d_in[8];
    const float* gA  = (const float*)d_in[9];
    const float* beA = (const float*)d_in[10];
    const float* mA  = (const float*)d_in[11];
    const float* vA  = (const float*)d_in[12];
    const float* wO  = (const float*)d_in[13];
    const float* bO  = (const float*)d_in[14];
    const float* gO  = (const float*)d_in[15];
    const float* beO = (const float*)d_in[16];
    const float* mO  = (const float*)d_in[17];
    const float* vO  = (const float*)d_in[18];

    float* out = (float*)d_out;
    float* S1o = out + (size_t)C2ELEMS;
    float* S2o = S1o + (size_t)SELEMS;

    cudaFuncSetAttribute(k1_c1c2, cudaFuncAttributeMaxDynamicSharedMemorySize, K1_SMEM);
    cudaFuncSetAttribute(k34_fused, cudaFuncAttributeMaxDynamicSharedMemorySize, K34_SMEM);

    k0_fold<<<1, 64>>>(w1,b1,g1,be1,m1,v1, wA,bA,gA,beA,mA,vA, wO,bO,gO,beO,mO,vO);
    k1_c1c2<<<dim3(NP/128, NB), 256, K1_SMEM>>>(x);
    k2a_gram_tc<<<dim3(4, 4, 2*NB), 256>>>();
    k2b_softmax<<<dim3(HW, NB), 256>>>(S1o, S2o);
    k34_fused<<<dim3(CW/64, 1, NB), 256, K34_SMEM>>>(out);
}

// round 15
// speedup vs baseline: 1.0748x; 1.0451x over previous
#include <cuda_runtime.h>
#include <cuda_fp16.h>
#include <cstdint>

// Problem constants: B=8, C=64, H=W=256
#define NB 8
#define NC 64
#define NP 65536              // H*W
#define HW 256                // H (== W)
#define CW 16384              // C*W
#define C2ELEMS (NB*NC*NP)    // 33554432
#define SELEMS  (NB*HW*HW)    // 524288
#define EPSBN 1e-5f
#define SLOPE 0.2f

// ---------------- scratch (device globals; no allocation allowed) -------------
__device__ float g_w1f[NC];
__device__ float g_b1f;
__device__ __half g_wAh[NC*NC];   // [o][c], fp16, BN-folded
__device__ float g_bAf[NC];
__device__ __half g_wOh[NC*NC];   // [o][c], fp16, BN-folded
__device__ float g_bOf[NC];
__device__ float g_C1[NB*NP];                 // (B,H,W)  2MB
__device__ __half g_C2h[C2ELEMS];             // fp16 C2 (GEMM B + residual), 67MB
__device__ float g_G[2*NB*HW*HW];             // gram matrices, 4MB
__device__ __half g_S12h[SELEMS];             // S1+S2 in fp16 (k34 GEMM A), 1MB

__device__ __forceinline__ float lrelu(float y) { return y >= 0.f ? y : SLOPE * y; }

__device__ __forceinline__ void mma_f16(float acc[4],
                                        uint32_t a0, uint32_t a1, uint32_t a2, uint32_t a3,
                                        uint32_t b0, uint32_t b1) {
    asm volatile(
        "mma.sync.aligned.m16n8k16.row.col.f32.f16.f16.f32 "
        "{%0,%1,%2,%3}, {%4,%5,%6,%7}, {%8,%9}, {%0,%1,%2,%3};"
        : "+f"(acc[0]), "+f"(acc[1]), "+f"(acc[2]), "+f"(acc[3])
        : "r"(a0), "r"(a1), "r"(a2), "r"(a3), "r"(b0), "r"(b1));
}

__device__ __forceinline__ void cp_async16(void* smem_dst, const void* gsrc) {
    uint32_t s = (uint32_t)__cvta_generic_to_shared(smem_dst);
    asm volatile("cp.async.cg.shared.global [%0], [%1], 16;" :: "r"(s), "l"(gsrc));
}

__device__ __forceinline__ void ldmx4(uint32_t r[4], const __half* p) {
    uint32_t ad = (uint32_t)__cvta_generic_to_shared(p);
    asm volatile("ldmatrix.sync.aligned.m8n8.x4.shared.b16 {%0,%1,%2,%3}, [%4];"
        : "=r"(r[0]), "=r"(r[1]), "=r"(r[2]), "=r"(r[3]) : "r"(ad));
}
__device__ __forceinline__ void ldmx4t(uint32_t r[4], const __half* p) {
    uint32_t ad = (uint32_t)__cvta_generic_to_shared(p);
    asm volatile("ldmatrix.sync.aligned.m8n8.x4.trans.shared.b16 {%0,%1,%2,%3}, [%4];"
        : "=r"(r[0]), "=r"(r[1]), "=r"(r[2]), "=r"(r[3]) : "r"(ad));
}

// ---------------- K0: fold BN into conv weights; fp16-round -------------------
__global__ void k0_fold(const float* __restrict__ w1, const float* __restrict__ b1,
                        const float* __restrict__ g1, const float* __restrict__ be1,
                        const float* __restrict__ m1, const float* __restrict__ v1,
                        const float* __restrict__ wA, const float* __restrict__ bA,
                        const float* __restrict__ gA, const float* __restrict__ beA,
                        const float* __restrict__ mA, const float* __restrict__ vA,
                        const float* __restrict__ wO, const float* __restrict__ bO,
                        const float* __restrict__ gO, const float* __restrict__ beO,
                        const float* __restrict__ mO, const float* __restrict__ vO) {
    int o = threadIdx.x;  // 0..63
    float aA = gA[o] * rsqrtf(vA[o] + EPSBN);
    float aO = gO[o] * rsqrtf(vO[o] + EPSBN);
    for (int c = 0; c < NC; c++) {
        g_wAh[o*NC + c] = __float2half_rn(aA * wA[o*NC + c]);
        g_wOh[o*NC + c] = __float2half_rn(aO * wO[o*NC + c]);
    }
    g_bAf[o] = aA * (bA[o] - mA[o]) + beA[o];
    g_bOf[o] = aO * (bO[o] - mO[o]) + beO[o];
    float a1 = g1[0] * rsqrtf(v1[0] + EPSBN);
    g_w1f[o] = a1 * w1[o];
    if (o == 0) g_b1f = a1 * (b1[0] - m1[0]) + be1[0];
}

// ---------------- K1: fused C1 (fp32) + C2 conv via fp16 k16 MMA --------------
__global__ __launch_bounds__(256) void k1_c1c2(const float* __restrict__ x) {
    extern __shared__ char k1sm[];
    float* xs = (float*)k1sm;                    // [64][132]
    __half* xh = (__half*)(k1sm + 33792);        // [64][136]
    int b = blockIdx.y;
    int p0 = blockIdx.x * 128;
    int tid = threadIdx.x;

    const float* xb = x + (size_t)b * NC * NP;
    #pragma unroll
    for (int t = 0; t < 8; t++) {
        int i = tid + t*256;
        int c = i >> 5, pq = i & 31;
        float4 v = *(const float4*)(xb + (size_t)c*NP + p0 + pq*4);
        *(float4*)&xs[c*132 + pq*4] = v;
        uint2 h;
        __half2 h0 = __floats2half2_rn(v.x, v.y);
        __half2 h1 = __floats2half2_rn(v.z, v.w);
        h.x = *(uint32_t*)&h0; h.y = *(uint32_t*)&h1;
        *(uint2*)&xh[c*136 + pq*4] = h;
    }
    __syncthreads();

    if (tid < 128) {
        float s = 0.f;
        #pragma unroll
        for (int c = 0; c < NC; c++) s += g_w1f[c] * xs[c*132 + tid];
        s += g_b1f;
        g_C1[(size_t)b*NP + p0 + tid] = lrelu(s);
    }

    int lane = tid & 31, warp = tid >> 5;
    int wm = warp >> 1;
    int wn = warp & 1;
    int g = lane >> 2, tig = lane & 3;
    int r0 = wm*16 + g;
    int b_row = ((lane >> 3) & 1) * 8 + (lane & 7);
    int b_col8 = (lane >> 4) * 8;

    float acc[8][4];
    #pragma unroll
    for (int nf = 0; nf < 8; nf++)
        #pragma unroll
        for (int r = 0; r < 4; r++) acc[nf][r] = 0.f;

    #pragma unroll
    for (int kf = 0; kf < 4; kf++) {
        int kk = kf*16;
        uint32_t a0 = *(const uint32_t*)&g_wAh[r0*NC + kk + 2*tig];
        uint32_t a1 = *(const uint32_t*)&g_wAh[(r0+8)*NC + kk + 2*tig];
        uint32_t a2 = *(const uint32_t*)&g_wAh[r0*NC + kk + 2*tig + 8];
        uint32_t a3 = *(const uint32_t*)&g_wAh[(r0+8)*NC + kk + 2*tig + 8];
        #pragma unroll
        for (int nb = 0; nb < 4; nb++) {
            uint32_t bb[4];
            ldmx4t(bb, &xh[(kk + b_row)*136 + wn*64 + nb*16 + b_col8]);
            mma_f16(acc[nb*2],   a0, a1, a2, a3, bb[0], bb[1]);
            mma_f16(acc[nb*2+1], a0, a1, a2, a3, bb[2], bb[3]);
        }
    }

    int o0 = wm*16 + g, o1 = o0 + 8;
    float bo0 = g_bAf[o0], bo1 = g_bAf[o1];
    #pragma unroll
    for (int nf = 0; nf < 8; nf++) {
        int col = p0 + wn*64 + nf*8 + tig*2;
        size_t off0 = (size_t)b*NC*NP + (size_t)o0*NP + col;
        size_t off1 = (size_t)b*NC*NP + (size_t)o1*NP + col;
        *(__half2*)&g_C2h[off0] = __floats2half2_rn(lrelu(acc[nf][0] + bo0),
                                                    lrelu(acc[nf][1] + bo0));
        *(__half2*)&g_C2h[off1] = __floats2half2_rn(lrelu(acc[nf][2] + bo1),
                                                    lrelu(acc[nf][3] + bo1));
    }
}
#define K1_SMEM 51200

// ---------------- K2a: Gram via fp16 hi/lo split tensor MMA -------------------
__global__ __launch_bounds__(256) void k2a_gram_tc() {
    __shared__ __half Ahi[64][40], Alo[64][40];   // [i][k]
    __shared__ __half Bhi[32][72], Blo[32][72];   // [k][j]
    int mat = blockIdx.z & 1;
    int b = blockIdx.z >> 1;
    int j0 = blockIdx.x * 64;
    int i0 = blockIdx.y * 64;
    const float* A = g_C1 + (size_t)b * NP;
    int tid = threadIdx.x;
    int lane = tid & 31, warp = tid >> 5;
    int wm = warp >> 1, wn = warp & 1;
    int g = lane >> 2, tig = lane & 3;
    int r0 = wm*16 + g;
    int b_row = ((lane >> 3) & 1) * 8 + (lane & 7);
    int b_col8 = (lane >> 4) * 8;

    float acc[4][4];
    #pragma unroll
    for (int nf = 0; nf < 4; nf++)
        #pragma unroll
        for (int r = 0; r < 4; r++) acc[nf][r] = 0.f;

    for (int k0 = 0; k0 < HW; k0 += 32) {
        if (k0 > 0) __syncthreads();
        if (mat == 0) {
            #pragma unroll
            for (int t = 0; t < 2; t++) {
                int idx = tid + t*256;
                int r = idx >> 3, q = (idx & 7) * 4;
                float4 v = *(const float4*)&A[(size_t)(i0+r)*HW + k0 + q];
                float h0=__half2float(__float2half_rn(v.x));
                float h1=__half2float(__float2half_rn(v.y));
                float h2=__half2float(__float2half_rn(v.z));
                float h3=__half2float(__float2half_rn(v.w));
                *(__half2*)&Ahi[r][q]   = __floats2half2_rn(v.x, v.y);
                *(__half2*)&Ahi[r][q+2] = __floats2half2_rn(v.z, v.w);
                *(__half2*)&Alo[r][q]   = __floats2half2_rn(v.x-h0, v.y-h1);
                *(__half2*)&Alo[r][q+2] = __floats2half2_rn(v.z-h2, v.w-h3);
            }
            #pragma unroll
            for (int t = 0; t < 2; t++) {
                int idx = tid + t*256;
                int jj = idx >> 3, q = (idx & 7) * 4;
                float4 v = *(const float4*)&A[(size_t)(j0+jj)*HW + k0 + q];
                float vv[4] = {v.x, v.y, v.z, v.w};
                #pragma unroll
                for (int e = 0; e < 4; e++) {
                    __half h = __float2half_rn(vv[e]);
                    Bhi[q+e][jj] = h;
                    Blo[q+e][jj] = __float2half_rn(vv[e] - __half2float(h));
                }
            }
        } else {
            #pragma unroll
            for (int t = 0; t < 2; t++) {
                int idx = tid + t*256;
                int kk = idx >> 4, q = (idx & 15) * 4;
                float4 v = *(const float4*)&A[(size_t)(k0+kk)*HW + i0 + q];
                float vv[4] = {v.x, v.y, v.z, v.w};
                #pragma unroll
                for (int e = 0; e < 4; e++) {
                    __half h = __float2half_rn(vv[e]);
                    Ahi[q+e][kk] = h;
                    Alo[q+e][kk] = __float2half_rn(vv[e] - __half2float(h));
                }
            }
            #pragma unroll
            for (int t = 0; t < 2; t++) {
                int idx = tid + t*256;
                int kk = idx >> 4, q = (idx & 15) * 4;
                float4 v = *(const float4*)&A[(size_t)(k0+kk)*HW + j0 + q];
                float h0=__half2float(__float2half_rn(v.x));
                float h1=__half2float(__float2half_rn(v.y));
                float h2=__half2float(__float2half_rn(v.z));
                float h3=__half2float(__float2half_rn(v.w));
                *(__half2*)&Bhi[kk][q]   = __floats2half2_rn(v.x, v.y);
                *(__half2*)&Bhi[kk][q+2] = __floats2half2_rn(v.z, v.w);
                *(__half2*)&Blo[kk][q]   = __floats2half2_rn(v.x-h0, v.y-h1);
                *(__half2*)&Blo[kk][q+2] = __floats2half2_rn(v.z-h2, v.w-h3);
            }
        }
        __syncthreads();

        #pragma unroll
        for (int kf = 0; kf < 2; kf++) {
            int kk = kf*16;
            uint32_t ah0 = *(const uint32_t*)&Ahi[r0][kk + 2*tig];
            uint32_t ah1 = *(const uint32_t*)&Ahi[r0+8][kk + 2*tig];
            uint32_t ah2 = *(const uint32_t*)&Ahi[r0][kk + 2*tig + 8];
            uint32_t ah3 = *(const uint32_t*)&Ahi[r0+8][kk + 2*tig + 8];
            uint32_t al0 = *(const uint32_t*)&Alo[r0][kk + 2*tig];
            uint32_t al1 = *(const uint32_t*)&Alo[r0+8][kk + 2*tig];
            uint32_t al2 = *(const uint32_t*)&Alo[r0][kk + 2*tig + 8];
            uint32_t al3 = *(const uint32_t*)&Alo[r0+8][kk + 2*tig + 8];
            #pragma unroll
            for (int nb = 0; nb < 2; nb++) {
                uint32_t bh[4], bl[4];
                ldmx4t(bh, &Bhi[kk + b_row][wn*32 + nb*16 + b_col8]);
                ldmx4t(bl, &Blo[kk + b_row][wn*32 + nb*16 + b_col8]);
                mma_f16(acc[nb*2],   ah0, ah1, ah2, ah3, bh[0], bh[1]);
                mma_f16(acc[nb*2],   ah0, ah1, ah2, ah3, bl[0], bl[1]);
                mma_f16(acc[nb*2],   al0, al1, al2, al3, bh[0], bh[1]);
                mma_f16(acc[nb*2+1], ah0, ah1, ah2, ah3, bh[2], bh[3]);
                mma_f16(acc[nb*2+1], ah0, ah1, ah2, ah3, bl[2], bl[3]);
                mma_f16(acc[nb*2+1], al0, al1, al2, al3, bh[2], bh[3]);
            }
        }
    }

    float* G = g_G + ((size_t)(mat*NB + b)) * HW * HW;
    int rg = i0 + wm*16 + g;
    #pragma unroll
    for (int nf = 0; nf < 4; nf++) {
        int col = j0 + wn*32 + nf*8 + tig*2;
        float2 v0; v0.x = acc[nf][0]; v0.y = acc[nf][1];
        float2 v1; v1.x = acc[nf][2]; v1.y = acc[nf][3];
        *(float2*)&G[(size_t)rg*HW + col] = v0;
        *(float2*)&G[(size_t)(rg+8)*HW + col] = v1;
    }
}

// ---------------- K2b: warp-per-row softmax -> S1,S2, S12h --------------------
// grid (HW/8, NB), 256 threads = 8 warps, one row per warp. Shfl-only reductions.
__global__ __launch_bounds__(256) void k2b_softmax(float* __restrict__ S1o,
                                                   float* __restrict__ S2o) {
    int b = blockIdx.y;
    int warp = threadIdx.x >> 5, lane = threadIdx.x & 31;
    int i = blockIdx.x * 8 + warp;
    float rr[2][8];
    #pragma unroll
    for (int mat = 0; mat < 2; mat++) {
        const float* row = g_G + (((size_t)(mat*NB + b))*HW + i)*HW + lane*8;
        float4 u0 = *(const float4*)row;
        float4 u1 = *(const float4*)(row + 4);
        float v[8] = {u0.x,u0.y,u0.z,u0.w,u1.x,u1.y,u1.z,u1.w};
        float m = v[0];
        #pragma unroll
        for (int j = 1; j < 8; j++) m = fmaxf(m, v[j]);
        #pragma unroll
        for (int o = 16; o; o >>= 1) m = fmaxf(m, __shfl_xor_sync(0xffffffffu, m, o));
        float s = 0.f;
        #pragma unroll
        for (int j = 0; j < 8; j++) { v[j] = expf(v[j] - m); s += v[j]; }
        #pragma unroll
        for (int o = 16; o; o >>= 1) s += __shfl_xor_sync(0xffffffffu, s, o);
        float inv = 1.f / s;
        #pragma unroll
        for (int j = 0; j < 8; j++) { v[j] *= inv; rr[mat][j] = v[j]; }
        float* dst = (mat == 0 ? S1o : S2o) + ((size_t)b*HW + i)*HW + lane*8;
        float4 w0; w0.x=v[0]; w0.y=v[1]; w0.z=v[2]; w0.w=v[3];
        float4 w1; w1.x=v[4]; w1.y=v[5]; w1.z=v[6]; w1.w=v[7];
        *(float4*)dst = w0;
        *(float4*)(dst + 4) = w1;
    }
    __half2 hs[4];
    #pragma unroll
    for (int j = 0; j < 4; j++)
        hs[j] = __floats2half2_rn(rr[0][2*j] + rr[1][2*j], rr[0][2*j+1] + rr[1][2*j+1]);
    *(uint4*)&g_S12h[((size_t)b*HW + i)*HW + lane*8] = *(uint4*)hs;
}

// ---------------- K34: fused GEMM (fp16 HMMA) + conv + smem residual ----------
// Block: 256 GEMM rows x 64 cols. grid (256, 1, NB), 256 thr (8 warps).
// A: 2-stage cp.async ring (2 x 256x40 halves = 40960B). B: persistent
// Ball[256][72] (36864B) — each 32-row slab loaded once, used by its MMA
// iteration AND by the epilogue residual add (saves the 67MB gmem re-read).
// ms[64][264] fp16 (33792B) aliases the A ring only. smem total 77824B.
__global__ __launch_bounds__(256) void k34_fused(float* __restrict__ out) {
    extern __shared__ char sm_raw[];
    __half* ring = (__half*)sm_raw;              // A stages: 2 x 10240 halves
    __half* Ball = (__half*)(sm_raw + 40960);    // [256][72]
    __half* ms = (__half*)sm_raw;                // [64][264], aliases A ring
    const int ASTG = 10240;                      // halves per A stage
    int b = blockIdx.z;
    int n0 = blockIdx.x * 64;
    const __half* Ag = g_S12h + (size_t)b * HW * HW;
    const __half* Bg = g_C2h + (size_t)b * NC * NP;
    int tid = threadIdx.x;
    int lane = tid & 31;
    int warp = tid >> 5;
    int g = lane >> 2, tig = lane & 3;

    int arow[4], aq[4];
    #pragma unroll
    for (int t = 0; t < 4; t++) { int idx = tid + t*256; arow[t] = idx >> 2; aq[t] = (idx & 3) * 8; }
    int brow = tid >> 3, bq = (tid & 7) * 8;

    int a_row = warp*32 + (lane & 15);
    int a_col8 = (lane >> 4) * 8;
    int b_row = ((lane >> 3) & 1) * 8 + (lane & 7);
    int b_col8 = (lane >> 4) * 8;

    // prologue: stage 0 (A) + B slab 0
    {
        __half* Ad = ring;
        #pragma unroll
        for (int t = 0; t < 4; t++)
            cp_async16(&Ad[arow[t]*40 + aq[t]], &Ag[(size_t)arow[t]*HW + aq[t]]);
        cp_async16(&Ball[brow*72 + bq], &Bg[(size_t)brow*CW + n0 + bq]);
        asm volatile("cp.async.commit_group;");
    }

    float acc[2][8][4];
    #pragma unroll
    for (int mf = 0; mf < 2; mf++)
        #pragma unroll
        for (int nf = 0; nf < 8; nf++)
            #pragma unroll
            for (int r = 0; r < 4; r++) acc[mf][nf][r] = 0.f;

    for (int k0 = 0; k0 < HW; k0 += 32) {
        int stg = (k0 >> 5) & 1;
        if (k0 + 32 < HW) {
            __half* Ad = ring + (stg^1)*ASTG;
            int kn = k0 + 32;
            #pragma unroll
            for (int t = 0; t < 4; t++)
                cp_async16(&Ad[arow[t]*40 + aq[t]], &Ag[(size_t)arow[t]*HW + kn + aq[t]]);
            cp_async16(&Ball[(kn + brow)*72 + bq], &Bg[(size_t)(kn+brow)*CW + n0 + bq]);
            asm volatile("cp.async.commit_group;");
            asm volatile("cp.async.wait_group 1;");
        } else {
            asm volatile("cp.async.wait_group 0;");
        }
        __syncthreads();

        const __half* As = ring + stg*ASTG;
        const __half* Bs = Ball + k0*72;

        #pragma unroll
        for (int kf = 0; kf < 2; kf++) {
            uint32_t a[2][4];
            #pragma unroll
            for (int mf = 0; mf < 2; mf++)
                ldmx4(a[mf], &As[(a_row + mf*16)*40 + kf*16 + a_col8]);
            #pragma unroll
            for (int nb = 0; nb < 4; nb++) {
                uint32_t bb[4];
                ldmx4t(bb, &Bs[(kf*16 + b_row)*72 + nb*16 + b_col8]);
                #pragma unroll
                for (int mf = 0; mf < 2; mf++) {
                    mma_f16(acc[mf][nb*2],   a[mf][0], a[mf][1], a[mf][2], a[mf][3], bb[0], bb[1]);
                    mma_f16(acc[mf][nb*2+1], a[mf][0], a[mf][1], a[mf][2], a[mf][3], bb[2], bb[3]);
                }
            }
        }
        __syncthreads();
    }

    // Stage accumulators to ms (aliases A ring only; Ball stays live)
    #pragma unroll
    for (int mf = 0; mf < 2; mf++) {
        #pragma unroll
        for (int nf = 0; nf < 8; nf++) {
            int row0 = warp*32 + mf*16 + g;
            int row1 = row0 + 8;
            int col  = nf*8 + tig*2;
            int c0 = row0 >> 2, hh0 = row0 & 3;
            int c1 = row1 >> 2, hh1 = row1 & 3;
            *(__half2*)&ms[c0*264 + hh0*64 + col] = __floats2half2_rn(acc[mf][nf][0], acc[mf][nf][1]);
            *(__half2*)&ms[c1*264 + hh1*64 + col] = __floats2half2_rn(acc[mf][nf][2], acc[mf][nf][3]);
        }
    }
    __syncthreads();

    // Conv phase (fp16 k16) + residual from Ball (smem)
    int wm = warp >> 1;
    int wn = warp & 1;
    int r0 = wm*16 + g;
    int o0 = r0, o1 = r0 + 8;
    float bo0 = g_bOf[o0], bo1 = g_bOf[o1];
    size_t bofs = (size_t)b * NC * NP;

    #pragma unroll
    for (int ph = 0; ph < 2; ph++) {
        int pix_base = ph*128 + wn*64;
        float acc2[8][4];
        #pragma unroll
        for (int nf = 0; nf < 8; nf++)
            #pragma unroll
            for (int r = 0; r < 4; r++) acc2[nf][r] = 0.f;

        #pragma unroll
        for (int kf = 0; kf < 4; kf++) {
            int kk = kf*16;
            uint32_t a0 = *(const uint32_t*)&g_wOh[r0*NC + kk + 2*tig];
            uint32_t a1 = *(const uint32_t*)&g_wOh[(r0+8)*NC + kk + 2*tig];
            uint32_t a2 = *(const uint32_t*)&g_wOh[r0*NC + kk + 2*tig + 8];
            uint32_t a3 = *(const uint32_t*)&g_wOh[(r0+8)*NC + kk + 2*tig + 8];
            #pragma unroll
            for (int nb = 0; nb < 4; nb++) {
                uint32_t bb[4];
                ldmx4t(bb, &ms[(kk + b_row)*264 + pix_base + nb*16 + b_col8]);
                mma_f16(acc2[nb*2],   a0, a1, a2, a3, bb[0], bb[1]);
                mma_f16(acc2[nb*2+1], a0, a1, a2, a3, bb[2], bb[3]);
            }
        }

        #pragma unroll
        for (int nf = 0; nf < 8; nf++) {
            int pix = pix_base + nf*8 + tig*2;
            int hh = pix >> 6, wl = pix & 63;
            size_t off0 = bofs + (size_t)(o0*4 + hh)*CW + n0 + wl;
            size_t off1 = bofs + (size_t)(o1*4 + hh)*CW + n0 + wl;
            float2 c20 = __half22float2(*(const __half2*)&Ball[(o0*4 + hh)*72 + wl]);
            float2 c21 = __half22float2(*(const __half2*)&Ball[(o1*4 + hh)*72 + wl]);
            float2 v0, v1;
            v0.x = c20.x + lrelu(acc2[nf][0] + bo0);
            v0.y = c20.y + lrelu(acc2[nf][1] + bo0);
            v1.x = c21.x + lrelu(acc2[nf][2] + bo1);
            v1.y = c21.y + lrelu(acc2[nf][3] + bo1);
            *(float2*)&out[off0] = v0;
            *(float2*)&out[off1] = v1;
        }
    }
}

#define K34_SMEM 77824

// ---------------- launch --------------------------------------------------------
extern "C" void kernel_launch(void* const* d_in, const int* in_sizes, int n_in,
                              void* d_out, int out_size) {
    const float* x   = (const float*)d_in[0];
    const float* w1  = (const float*)d_in[1];
    const float* b1  = (const float*)d_in[2];
    const float* g1  = (const float*)d_in[3];
    const float* be1 = (const float*)d_in[4];
    const float* m1  = (const float*)d_in[5];
    const float* v1  = (const float*)d_in[6];
    const float* wA  = (const float*)d_in[7];
    const float* bA  = (const float*)d_in[8];
    const float* gA  = (const float*)d_in[9];
    const float* beA = (const float*)d_in[10];
    const float* mA  = (const float*)d_in[11];
    const float* vA  = (const float*)d_in[12];
    const float* wO  = (const float*)d_in[13];
    const float* bO  = (const float*)d_in[14];
    const float* gO  = (const float*)d_in[15];
    const float* beO = (const float*)d_in[16];
    const float* mO  = (const float*)d_in[17];
    const float* vO  = (const float*)d_in[18];

    float* out = (float*)d_out;
    float* S1o = out + (size_t)C2ELEMS;
    float* S2o = S1o + (size_t)SELEMS;

    cudaFuncSetAttribute(k1_c1c2, cudaFuncAttributeMaxDynamicSharedMemorySize, K1_SMEM);
    cudaFuncSetAttribute(k34_fused, cudaFuncAttributeMaxDynamicSharedMemorySize, K34_SMEM);

    k0_fold<<<1, 64>>>(w1,b1,g1,be1,m1,v1, wA,bA,gA,beA,mA,vA, wO,bO,gO,beO,mO,vO);
    k1_c1c2<<<dim3(NP/128, NB), 256, K1_SMEM>>>(x);
    k2a_gram_tc<<<dim3(4, 4, 2*NB), 256>>>();
    k2b_softmax<<<dim3(HW/8, NB), 256>>>(S1o, S2o);
    k34_fused<<<dim3(CW/64, 1, NB), 256, K34_SMEM>>>(out);
}